// round 9
// baseline (speedup 1.0000x reference)
#include <cuda_runtime.h>
#include <math_constants.h>

#define B_      8
#define H_      32
#define DK_     128
#define DM_     4096
#define MAXLEN_ 4096
#define SPLIT_  4
#define KSPLIT_ 4

// Scratch (no allocation allowed in kernel_launch)
__device__ float g_qp[KSPLIT_][B_ * DM_];   // q projection partials
__device__ float g_kp[KSPLIT_][B_ * DM_];
__device__ float g_vp[KSPLIT_][B_ * DM_];
__device__ float g_op[KSPLIT_][B_ * DM_];   // output projection partials
__device__ float g_attn[B_ * DM_];
__device__ float g_pm[B_ * H_ * SPLIT_];
__device__ float g_pl[B_ * H_ * SPLIT_];
__device__ float g_pa[B_ * H_ * SPLIT_ * DK_];

__device__ __forceinline__ float dot4(float4 a, float4 b) {
    return a.x * b.x + a.y * b.y + a.z * b.z + a.w * b.w;
}
__device__ __forceinline__ float4 add4(float4 a, float4 b) {
    return make_float4(a.x + b.x, a.y + b.y, a.z + b.z, a.w + b.w);
}
__device__ __forceinline__ unsigned smem_u32(const void* p) {
    return (unsigned)__cvta_generic_to_shared(p);
}

// ---------------------------------------------------------------------------
// Split-K GEMV partial with cp.async W pipeline.
// Block: 256 thr = 8 warps x 4 rows = 32 rows; slice = DM/KSPLIT = 1024 cols.
// W streamed gmem->smem with cp.async.cg in 16KB stages (32 rows x 128 cols),
// NSTAGES=3 -> 32KB in flight per CTA independent of register pressure.
// x slice (32KB) staged in smem. smem total 80KB -> 2 CTAs/SM.
// Epilogue: butterfly transpose-reduce -> 31 shuffles, 1 STG per lane.
// ---------------------------------------------------------------------------
#define SLICE4_  (DM_ / KSPLIT_ / 4)   // float4 cols per slice (256)
#define STG4_    32                    // float4 cols per stage (128 floats)
#define NIT_     (SLICE4_ / STG4_)     // stages per slice (8)
#define NSTAGES_ 3
#define STGSZ_   (32 * STG4_)          // float4 elems per stage buffer (1024)

__device__ __forceinline__ void issue_stage(const float* __restrict__ W,
                                            int row0_blk, int gcol4,
                                            float4* wbuf, int tid) {
    // 1024 x 16B chunks; 256 threads x 4 each. j -> (row = j>>5, col4 = j&31)
    #pragma unroll
    for (int k = 0; k < 4; k++) {
        const int j   = tid + k * 256;
        const int row = j >> 5;
        const int c4  = j & 31;
        const float4* src = (const float4*)(W + (size_t)(row0_blk + row) * DM_)
                          + gcol4 + c4;
        const unsigned dst = smem_u32(wbuf + j);
        asm volatile("cp.async.cg.shared.global [%0], [%1], 16;"
                     :: "r"(dst), "l"(src));
    }
}

__device__ __forceinline__ void proj_body(const float4* __restrict__ x4,
                                          const float* __restrict__ W,
                                          float* __restrict__ yp,
                                          int kslice, float4* sm) {
    const int tid  = threadIdx.x;
    const int warp = tid >> 5;
    const int lane = tid & 31;
    const int row0_blk = blockIdx.x * 32;
    const int row0 = row0_blk + warp * 4;
    const int cbase = kslice * SLICE4_;       // float4 column base of slice

    float4* xs4 = sm;                         // [B_][SLICE4_]  (32 KB)
    float4* ws  = sm + B_ * SLICE4_;          // [NSTAGES_][STGSZ_] (48 KB)

    // stage x slice into smem (plain loads; ordered by the first sync)
    #pragma unroll
    for (int i = tid; i < B_ * SLICE4_; i += 256) {
        const int b = i / SLICE4_;
        const int c = i - b * SLICE4_;
        xs4[i] = __ldg(x4 + b * (DM_ / 4) + cbase + c);
    }

    // prologue: issue stages 0..NSTAGES_-2
    #pragma unroll
    for (int st = 0; st < NSTAGES_ - 1; st++) {
        issue_stage(W, row0_blk, cbase + st * STG4_, ws + st * STGSZ_, tid);
        asm volatile("cp.async.commit_group;");
    }

    float acc[32];                            // acc[r*8+b]
    #pragma unroll
    for (int i = 0; i < 32; i++) acc[i] = 0.f;

    #pragma unroll
    for (int it = 0; it < NIT_; ++it) {
        // stage `it` arrived when <= NSTAGES_-2 groups pending
        asm volatile("cp.async.wait_group %0;" :: "n"(NSTAGES_ - 2));
        __syncthreads();

        // issue stage it+NSTAGES_-1 into the buffer freed last iteration
        if (it + NSTAGES_ - 1 < NIT_) {
            const int st = it + NSTAGES_ - 1;
            issue_stage(W, row0_blk, cbase + st * STG4_,
                        ws + (st % NSTAGES_) * STGSZ_, tid);
        }
        asm volatile("cp.async.commit_group;");  // always commit (may be empty)

        // compute on stage it
        const float4* wst = ws + (it % NSTAGES_) * STGSZ_;
        const float4 wa0 = wst[(warp * 4 + 0) * STG4_ + lane];
        const float4 wa1 = wst[(warp * 4 + 1) * STG4_ + lane];
        const float4 wa2 = wst[(warp * 4 + 2) * STG4_ + lane];
        const float4 wa3 = wst[(warp * 4 + 3) * STG4_ + lane];
        const int xc = it * STG4_ + lane;
        #pragma unroll
        for (int b = 0; b < B_; b++) {
            const float4 xa = xs4[b * SLICE4_ + xc];
            acc[0 * 8 + b] += dot4(wa0, xa);
            acc[1 * 8 + b] += dot4(wa1, xa);
            acc[2 * 8 + b] += dot4(wa2, xa);
            acc[3 * 8 + b] += dot4(wa3, xa);
        }
    }

    // Butterfly transpose-reduce: lane L ends holding full sum of acc[L].
    #pragma unroll
    for (int o = 16; o >= 1; o >>= 1) {
        const bool up = (lane & o) != 0;
        #pragma unroll
        for (int k = 0; k < o; k++) {
            const float keep = up ? acc[k + o] : acc[k];
            const float send = up ? acc[k]     : acc[k + o];
            acc[k] = keep + __shfl_xor_sync(0xffffffffu, send, o);
        }
    }
    const int r = lane >> 3;
    const int b = lane & 7;
    yp[b * DM_ + row0 + r] = acc[0];
}

#define PROJ_SMEM_ ((B_ * SLICE4_ + NSTAGES_ * STGSZ_) * (int)sizeof(float4))

__global__ void __launch_bounds__(256, 2)
proj_qkv_kernel(const float* __restrict__ q_in, const float* __restrict__ k_in,
                const float* __restrict__ v_in,
                const float* __restrict__ Wq, const float* __restrict__ Wk,
                const float* __restrict__ Wv) {
    extern __shared__ float4 sm[];
    const int ks = blockIdx.y;
    const float* x; const float* W; float* y;
    if (blockIdx.z == 0)      { x = q_in; W = Wq; y = g_qp[ks]; }
    else if (blockIdx.z == 1) { x = k_in; W = Wk; y = g_kp[ks]; }
    else                      { x = v_in; W = Wv; y = g_vp[ks]; }
    proj_body((const float4*)x, W, y, ks, sm);
}

__global__ void __launch_bounds__(256, 2)
proj_out_kernel(const float* __restrict__ Wo) {
    extern __shared__ float4 sm[];
    proj_body((const float4*)g_attn, Wo, g_op[blockIdx.y], blockIdx.y, sm);
}

__global__ void __launch_bounds__(256)
final_add_kernel(const float* __restrict__ bo, float* __restrict__ out) {
    const int i = blockIdx.x * 256 + threadIdx.x;   // i in [0, B_*DM_)
    out[i] = (g_op[0][i] + g_op[1][i]) + (g_op[2][i] + g_op[3][i])
           + bo[i & (DM_ - 1)];
}

// ---------------------------------------------------------------------------
// Attention, split-K over keys (at HBM roofline — unchanged).
// ---------------------------------------------------------------------------
__global__ void __launch_bounds__(256)
attn_kernel(const float* __restrict__ kc, const float* __restrict__ vc,
            const float* __restrict__ bq, const float* __restrict__ bk,
            const float* __restrict__ bv, const int* __restrict__ cache_len_p) {
    const int bh = blockIdx.x;
    const int b  = bh >> 5;
    const int h  = bh & 31;
    const int s  = blockIdx.y;
    const int L  = cache_len_p[0] + 1;
    const int Lm1 = L - 1;
    const int chunk = (L + SPLIT_ - 1) / SPLIT_;
    const int start = s * chunk;
    const int end   = min(start + chunk, L);

    const int tid  = threadIdx.x;
    const int warp = tid >> 5;
    const int lane = tid & 31;

    const int voff = b * DM_ + h * DK_;
    const float scale = 0.08838834764831843f; // 1/sqrt(128)

    float4 q4   = ((const float4*)(bq + h * DK_))[lane];
    float4 Knew = ((const float4*)(bk + h * DK_))[lane];
    float4 Vnew = ((const float4*)(bv + h * DK_))[lane];
    #pragma unroll
    for (int ks = 0; ks < KSPLIT_; ks++) {
        q4   = add4(q4,   ((const float4*)(g_qp[ks] + voff))[lane]);
        Knew = add4(Knew, ((const float4*)(g_kp[ks] + voff))[lane]);
        Vnew = add4(Vnew, ((const float4*)(g_vp[ks] + voff))[lane]);
    }
    q4.x *= scale; q4.y *= scale; q4.z *= scale; q4.w *= scale;

    const float4* kb = (const float4*)(kc + (((size_t)b * H_ + h) * (size_t)MAXLEN_) * DK_);
    const float4* vb = (const float4*)(vc + (((size_t)b * H_ + h) * (size_t)MAXLEN_) * DK_);

    float m = -CUDART_INF_F;
    float lsum = 0.f;
    float4 a = make_float4(0.f, 0.f, 0.f, 0.f);

    int key = start + warp;
    for (; key + 24 < end; key += 32) {
        const int k1 = key, k2 = key + 8, k3 = key + 16, k4 = key + 24;
        float4 K1 = __ldcs(kb + (size_t)k1 * 32 + lane);
        float4 K2 = __ldcs(kb + (size_t)k2 * 32 + lane);
        float4 K3 = __ldcs(kb + (size_t)k3 * 32 + lane);
        float4 K4 = __ldcs(kb + (size_t)k4 * 32 + lane);
        float4 V1 = __ldcs(vb + (size_t)k1 * 32 + lane);
        float4 V2 = __ldcs(vb + (size_t)k2 * 32 + lane);
        float4 V3 = __ldcs(vb + (size_t)k3 * 32 + lane);
        float4 V4 = __ldcs(vb + (size_t)k4 * 32 + lane);
        if (k1 == Lm1) { K1 = Knew; V1 = Vnew; }
        if (k2 == Lm1) { K2 = Knew; V2 = Vnew; }
        if (k3 == Lm1) { K3 = Knew; V3 = Vnew; }
        if (k4 == Lm1) { K4 = Knew; V4 = Vnew; }

        float s1 = dot4(q4, K1);
        float s2 = dot4(q4, K2);
        float s3 = dot4(q4, K3);
        float s4 = dot4(q4, K4);
        #pragma unroll
        for (int o = 16; o > 0; o >>= 1) {
            s1 += __shfl_xor_sync(0xffffffffu, s1, o);
            s2 += __shfl_xor_sync(0xffffffffu, s2, o);
            s3 += __shfl_xor_sync(0xffffffffu, s3, o);
            s4 += __shfl_xor_sync(0xffffffffu, s4, o);
        }

        const float mn = fmaxf(fmaxf(m, fmaxf(s1, s2)), fmaxf(s3, s4));
        const float corr = __expf(m - mn);
        const float p1 = __expf(s1 - mn);
        const float p2 = __expf(s2 - mn);
        const float p3 = __expf(s3 - mn);
        const float p4 = __expf(s4 - mn);
        lsum = lsum * corr + (p1 + p2) + (p3 + p4);
        a.x = a.x * corr + p1 * V1.x + p2 * V2.x + p3 * V3.x + p4 * V4.x;
        a.y = a.y * corr + p1 * V1.y + p2 * V2.y + p3 * V3.y + p4 * V4.y;
        a.z = a.z * corr + p1 * V1.z + p2 * V2.z + p3 * V3.z + p4 * V4.z;
        a.w = a.w * corr + p1 * V1.w + p2 * V2.w + p3 * V3.w + p4 * V4.w;
        m = mn;
    }
    for (; key < end; key += 8) {
        float4 K1 = __ldcs(kb + (size_t)key * 32 + lane);
        float4 V1 = __ldcs(vb + (size_t)key * 32 + lane);
        if (key == Lm1) { K1 = Knew; V1 = Vnew; }
        float s1 = dot4(q4, K1);
        #pragma unroll
        for (int o = 16; o > 0; o >>= 1) s1 += __shfl_xor_sync(0xffffffffu, s1, o);
        const float mn = fmaxf(m, s1);
        const float corr = __expf(m - mn);
        const float p1 = __expf(s1 - mn);
        lsum = lsum * corr + p1;
        a.x = a.x * corr + p1 * V1.x;
        a.y = a.y * corr + p1 * V1.y;
        a.z = a.z * corr + p1 * V1.z;
        a.w = a.w * corr + p1 * V1.w;
        m = mn;
    }

    // cross-warp combine -> unnormalized block partial
    __shared__ float  sm_m[8];
    __shared__ float  sm_l[8];
    __shared__ float4 sm_a[8][32];
    if (lane == 0) { sm_m[warp] = m; sm_l[warp] = lsum; }
    sm_a[warp][lane] = a;
    __syncthreads();

    if (tid < 128) {
        float M = sm_m[0];
        #pragma unroll
        for (int w = 1; w < 8; w++) M = fmaxf(M, sm_m[w]);
        float Ls = 0.f, o = 0.f;
        const float* sa = (const float*)sm_a;  // [8][128]
        #pragma unroll
        for (int w = 0; w < 8; w++) {
            const float e = __expf(sm_m[w] - M);
            Ls += e * sm_l[w];
            o  += e * sa[w * 128 + tid];
        }
        const int idx = bh * SPLIT_ + s;
        g_pa[idx * DK_ + tid] = o;
        if (tid == 0) { g_pm[idx] = M; g_pl[idx] = Ls; }
    }
}

__global__ void __launch_bounds__(128)
attn_reduce_kernel() {
    const int bh = blockIdx.x;
    const int d  = threadIdx.x;
    float M = -CUDART_INF_F;
    #pragma unroll
    for (int s = 0; s < SPLIT_; s++) M = fmaxf(M, g_pm[bh * SPLIT_ + s]);
    float Ls = 0.f, o = 0.f;
    #pragma unroll
    for (int s = 0; s < SPLIT_; s++) {
        const int idx = bh * SPLIT_ + s;
        const float e = __expf(g_pm[idx] - M);
        Ls += e * g_pl[idx];
        o  += e * g_pa[idx * DK_ + d];
    }
    g_attn[bh * DK_ + d] = o / Ls;
}

// ---------------------------------------------------------------------------
extern "C" void kernel_launch(void* const* d_in, const int* in_sizes, int n_in,
                              void* d_out, int out_size) {
    const float* query = (const float*)d_in[0];
    const float* keyv  = (const float*)d_in[1];
    const float* value = (const float*)d_in[2];
    const float* kc    = (const float*)d_in[3];
    const float* vc    = (const float*)d_in[4];
    const float* Wq    = (const float*)d_in[5];
    const float* bq    = (const float*)d_in[6];
    const float* Wk    = (const float*)d_in[7];
    const float* bk    = (const float*)d_in[8];
    const float* Wv    = (const float*)d_in[9];
    const float* bv    = (const float*)d_in[10];
    const float* Wo    = (const float*)d_in[11];
    const float* bo    = (const float*)d_in[12];
    const int*   clp   = (const int*)d_in[13];

    cudaFuncSetAttribute(proj_qkv_kernel, cudaFuncAttributeMaxDynamicSharedMemorySize, PROJ_SMEM_);
    cudaFuncSetAttribute(proj_out_kernel, cudaFuncAttributeMaxDynamicSharedMemorySize, PROJ_SMEM_);

    dim3 gqkv(DM_ / 32, KSPLIT_, 3);
    proj_qkv_kernel<<<gqkv, 256, PROJ_SMEM_>>>(query, keyv, value, Wq, Wk, Wv);
    dim3 gattn(B_ * H_, SPLIT_);
    attn_kernel<<<gattn, 256>>>(kc, vc, bq, bk, bv, clp);
    attn_reduce_kernel<<<B_ * H_, 128>>>();
    dim3 gout(DM_ / 32, KSPLIT_);
    proj_out_kernel<<<gout, 256, PROJ_SMEM_>>>(Wo);
    final_add_kernel<<<B_ * DM_ / 256, 256>>>(bo, (float*)d_out);
}